// round 16
// baseline (speedup 1.0000x reference)
#include <cuda_runtime.h>
#include <cstdint>

// Dense 2D spatial transformer (bilinear warp, zero-padded border).
// R16: R14's 3-stage pipeline (flow g+2 | gathers g+1 | combine g) with the
// flow prefetch moved from registers to cp.async (LDGSTS) into a 2-slot smem
// ring. Each thread copies and reads only its own column -> no barriers;
// commit_group/wait_group 1 implements prefetch distance 2. This removes the
// flow-buffer register state so occupancy can rise to 6 blocks/SM without
// constraining gather-load scheduling (the R15 failure mode).
//
// Reference semantics (padded coords in [0,4097], zero border):
//   H_up = flow_h + h + 1 ; W_up = flow_w + w + 1
//   hf = clip(floor(H_up),0,4097); hc = clip(hf+1,0,4097); same for w
//   dH = hc - H_up; dW = wc - W_up   (weights from CLIPPED coords)
//   out = v00*dW*dH + v10*dW*(1-dH) + v01*(1-dW)*dH + v11*(1-dW)*(1-dH)

#define H_DIM 4096
#define W_DIM 4096
#define HP_MAX 4097
#define RPT 2      // rows per pipeline stage
#define NITER 8    // stages per block -> 16 rows per block

__device__ __forceinline__ float fetch_padded(const float* __restrict__ img, int h, int w) {
    bool in = ((unsigned)(h - 1) < (unsigned)H_DIM) & ((unsigned)(w - 1) < (unsigned)W_DIM);
    int idx = ((h - 1) << 12) + (w - 1);
    return in ? __ldg(img + idx) : 0.0f;
}

__device__ __forceinline__ void cp_async4(float* smem_dst, const float* gmem_src) {
    unsigned saddr = (unsigned)__cvta_generic_to_shared(smem_dst);
    asm volatile("cp.async.ca.shared.global [%0], [%1], 4;" :: "r"(saddr), "l"(gmem_src));
}
__device__ __forceinline__ void cp_commit() {
    asm volatile("cp.async.commit_group;");
}
__device__ __forceinline__ void cp_wait1() {
    asm volatile("cp.async.wait_group 1;");
}

__global__ void __launch_bounds__(256, 6)
dense_warp_kernel(const float* __restrict__ img,
                  const float* __restrict__ flowH,
                  const float* __restrict__ flowW,
                  float* __restrict__ out) {
    // flow ring: [slot][plane][row-in-stage][column(thread)]
    __shared__ float sfl[2][2][RPT][256];

    const int tid = threadIdx.x;
    const int w  = (blockIdx.x << 8) + tid;
    const int h0 = blockIdx.y * (RPT * NITER);
    const int base0 = (h0 << 12) + w;
    const float wp1 = (float)(w + 1);

    float v00[2][RPT], v01[2][RPT], v10[2][RPT], v11[2][RPT];
    float dH[2][RPT], dW[2][RPT];

    // flow-group q lives in slot q&1
    auto issue_flow = [&](int q) {
        const int qbase = base0 + ((q * RPT) << 12);
        #pragma unroll
        for (int k = 0; k < RPT; k++) {
            cp_async4(&sfl[q & 1][0][k][tid], flowH + qbase + (k << 12));
            cp_async4(&sfl[q & 1][1][k][tid], flowW + qbase + (k << 12));
        }
    };

    // ---- prologue: flow for groups 0 and 1 ----
    issue_flow(0); cp_commit();
    issue_flow(1); cp_commit();

    // gather-issue for group g (flow in slot g&1) into buffer slot s
    auto gather_stage = [&](int s, int g) {
        const float hp1 = (float)(h0 + g * RPT + 1);
        const int fs = g & 1;
        #pragma unroll
        for (int k = 0; k < RPT; k++) {
            float Hu = sfl[fs][0][k][tid] + hp1 + (float)k;
            float Wu = sfl[fs][1][k][tid] + wp1;

            float fhf = floorf(Hu);
            float fwf = floorf(Wu);
            int hf = (int)fhf;
            int wf = (int)fwf;

            if (((unsigned)(hf - 1) <= 4094u) & ((unsigned)(wf - 1) <= 4094u)) {
                dH[s][k] = (fhf + 1.0f) - Hu;
                dW[s][k] = (fwf + 1.0f) - Wu;
                int idx = (hf << 12) + wf - (W_DIM + 1);   // (hf-1)*4096 + (wf-1)
                v00[s][k] = __ldg(img + idx);
                v01[s][k] = __ldg(img + idx + 1);
                v10[s][k] = __ldg(img + idx + W_DIM);
                v11[s][k] = __ldg(img + idx + W_DIM + 1);
            } else {
                int hc = hf + 1, wc = wf + 1;
                int hfc = min(max(hf, 0), HP_MAX);
                int hcc = min(max(hc, 0), HP_MAX);
                int wfc = min(max(wf, 0), HP_MAX);
                int wcc = min(max(wc, 0), HP_MAX);
                dH[s][k] = (float)hcc - Hu;
                dW[s][k] = (float)wcc - Wu;
                v00[s][k] = fetch_padded(img, hfc, wfc);
                v01[s][k] = fetch_padded(img, hfc, wcc);
                v10[s][k] = fetch_padded(img, hcc, wfc);
                v11[s][k] = fetch_padded(img, hcc, wcc);
            }
        }
    };

    // prologue: gathers for group 0 (slot 0). wait_group 1 -> group 0 arrived.
    cp_wait1();
    gather_stage(0, 0);

    // ---- main loop ----
    #pragma unroll
    for (int g = 0; g < NITER; g++) {
        const int cur = g & 1;
        const int nxt = cur ^ 1;

        // stage A: flow prefetch for group g+2 into slot (g+2)&1 == cur
        //          (slot cur's flow group g was consumed at iter g-1)
        if (g + 2 < NITER) issue_flow(g + 2);
        cp_commit();   // uniform group counting (empty groups near the tail)

        // stage B: gathers for group g+1 (flow group g+1 arrived once <=1
        //          newer commit group is outstanding)
        if (g + 1 < NITER) {
            cp_wait1();
            gather_stage(nxt, g + 1);
        }

        // stage C: combine + store group g (gathers issued at iter g-1)
        const int gbase = base0 + ((g * RPT) << 12);
        #pragma unroll
        for (int k = 0; k < RPT; k++) {
            float eH = 1.0f - dH[cur][k];
            float eW = 1.0f - dW[cur][k];
            float a = fmaf(eW, v01[cur][k], dW[cur][k] * v00[cur][k]);
            float b = fmaf(eW, v11[cur][k], dW[cur][k] * v10[cur][k]);
            out[gbase + (k << 12)] = fmaf(eH, b, dH[cur][k] * a);
        }
    }
}

extern "C" void kernel_launch(void* const* d_in, const int* in_sizes, int n_in,
                              void* d_out, int out_size) {
    const float* img   = (const float*)d_in[0];
    const float* flowH = (const float*)d_in[1];
    const float* flowW = (const float*)d_in[1] + (size_t)H_DIM * W_DIM;
    float* out = (float*)d_out;

    dim3 grid(W_DIM / 256, H_DIM / (RPT * NITER));   // 16 x 256 = 4096 blocks
    dense_warp_kernel<<<grid, 256>>>(img, flowH, flowW, out);
}

// round 17
// speedup vs baseline: 1.4284x; 1.4284x over previous
#include <cuda_runtime.h>
#include <cstdint>

// Dense 2D spatial transformer (bilinear warp, zero-padded border).
// R17: R14's 3-stage pipeline with a doubled stage size (RPT=4, NITER=4):
//   iter g:  flow load (g+2) | gather issue (g+1) | combine+store (g)
// 16 gathers in flight per warp (vs 8 in R14) at 4 CTAs/SM. Vertical
// 32-column-strip warp footprint throughout (R9 result). All state in
// registers (cp.async was a regression, R16).
//
// Reference semantics (padded coords in [0,4097], zero border):
//   H_up = flow_h + h + 1 ; W_up = flow_w + w + 1
//   hf = clip(floor(H_up),0,4097); hc = clip(hf+1,0,4097); same for w
//   dH = hc - H_up; dW = wc - W_up   (weights from CLIPPED coords)
//   out = v00*dW*dH + v10*dW*(1-dH) + v01*(1-dW)*dH + v11*(1-dW)*(1-dH)

#define H_DIM 4096
#define W_DIM 4096
#define HP_MAX 4097
#define RPT 4      // rows per pipeline stage
#define NITER 4    // stages per block -> 16 rows per block

__device__ __forceinline__ float fetch_padded(const float* __restrict__ img, int h, int w) {
    bool in = ((unsigned)(h - 1) < (unsigned)H_DIM) & ((unsigned)(w - 1) < (unsigned)W_DIM);
    int idx = ((h - 1) << 12) + (w - 1);
    return in ? __ldg(img + idx) : 0.0f;
}

__global__ void __launch_bounds__(256, 4)
dense_warp_kernel(const float* __restrict__ img,
                  const float* __restrict__ flowH,
                  const float* __restrict__ flowW,
                  float* __restrict__ out) {
    const int w  = (blockIdx.x << 8) + threadIdx.x;
    const int h0 = blockIdx.y * (RPT * NITER);
    const int base0 = (h0 << 12) + w;
    const float wp1 = (float)(w + 1);

    float fh[2][RPT], fw[2][RPT];
    float v00[2][RPT], v01[2][RPT], v10[2][RPT], v11[2][RPT];
    float dH[2][RPT], dW[2][RPT];

    // ---- prologue: flow for groups 0 and 1 ----
    #pragma unroll
    for (int k = 0; k < RPT; k++) {
        fh[0][k] = __ldg(flowH + base0 + (k << 12));
        fw[0][k] = __ldg(flowW + base0 + (k << 12));
    }
    #pragma unroll
    for (int k = 0; k < RPT; k++) {
        fh[1][k] = __ldg(flowH + base0 + ((RPT + k) << 12));
        fw[1][k] = __ldg(flowW + base0 + ((RPT + k) << 12));
    }

    // gather-issue for group g (flow in slot g&1) into buffer slot s
    auto gather_stage = [&](int s, int g) {
        const float hp1 = (float)(h0 + g * RPT + 1);
        #pragma unroll
        for (int k = 0; k < RPT; k++) {
            float Hu = fh[s][k] + hp1 + (float)k;
            float Wu = fw[s][k] + wp1;

            float fhf = floorf(Hu);
            float fwf = floorf(Wu);
            int hf = (int)fhf;
            int wf = (int)fwf;

            if (((unsigned)(hf - 1) <= 4094u) & ((unsigned)(wf - 1) <= 4094u)) {
                dH[s][k] = (fhf + 1.0f) - Hu;
                dW[s][k] = (fwf + 1.0f) - Wu;
                int idx = (hf << 12) + wf - (W_DIM + 1);   // (hf-1)*4096 + (wf-1)
                v00[s][k] = __ldg(img + idx);
                v01[s][k] = __ldg(img + idx + 1);
                v10[s][k] = __ldg(img + idx + W_DIM);
                v11[s][k] = __ldg(img + idx + W_DIM + 1);
            } else {
                int hc = hf + 1, wc = wf + 1;
                int hfc = min(max(hf, 0), HP_MAX);
                int hcc = min(max(hc, 0), HP_MAX);
                int wfc = min(max(wf, 0), HP_MAX);
                int wcc = min(max(wc, 0), HP_MAX);
                dH[s][k] = (float)hcc - Hu;
                dW[s][k] = (float)wcc - Wu;
                v00[s][k] = fetch_padded(img, hfc, wfc);
                v01[s][k] = fetch_padded(img, hfc, wcc);
                v10[s][k] = fetch_padded(img, hcc, wfc);
                v11[s][k] = fetch_padded(img, hcc, wcc);
            }
        }
    };

    // prologue: gathers for group 0 (slot 0, flow slot 0)
    gather_stage(0, 0);

    // ---- main loop ----
    #pragma unroll
    for (int g = 0; g < NITER; g++) {
        const int cur = g & 1;
        const int nxt = cur ^ 1;

        // stage A: flow load for group g+2 into flow slot (g+2)&1 == cur
        //          (slot cur's flow, group g, was consumed at iter g-1)
        if (g + 2 < NITER) {
            const int nbase = base0 + (((g + 2) * RPT) << 12);
            #pragma unroll
            for (int k = 0; k < RPT; k++) {
                fh[cur][k] = __ldg(flowH + nbase + (k << 12));
                fw[cur][k] = __ldg(flowW + nbase + (k << 12));
            }
        }

        // stage B: gather issue for group g+1 (v slot nxt, flow slot (g+1)&1 == nxt)
        if (g + 1 < NITER) {
            gather_stage(nxt, g + 1);
        }

        // stage C: combine + store group g (gathers issued at iter g-1)
        const int gbase = base0 + ((g * RPT) << 12);
        #pragma unroll
        for (int k = 0; k < RPT; k++) {
            float eH = 1.0f - dH[cur][k];
            float eW = 1.0f - dW[cur][k];
            float a = fmaf(eW, v01[cur][k], dW[cur][k] * v00[cur][k]);
            float b = fmaf(eW, v11[cur][k], dW[cur][k] * v10[cur][k]);
            out[gbase + (k << 12)] = fmaf(eH, b, dH[cur][k] * a);
        }
    }
}

extern "C" void kernel_launch(void* const* d_in, const int* in_sizes, int n_in,
                              void* d_out, int out_size) {
    const float* img   = (const float*)d_in[0];
    const float* flowH = (const float*)d_in[1];
    const float* flowW = (const float*)d_in[1] + (size_t)H_DIM * W_DIM;
    float* out = (float*)d_out;

    dim3 grid(W_DIM / 256, H_DIM / (RPT * NITER));   // 16 x 256 = 4096 blocks
    dense_warp_kernel<<<grid, 256>>>(img, flowH, flowW, out);
}